// round 3
// baseline (speedup 1.0000x reference)
#include <cuda_runtime.h>
#include <cuda_bf16.h>

#define KNB 32
#define MAXPL 8   // supports molecules up to 256 atoms fully; evict-max fallback beyond
#define CUTOFF 5.0f
#define INVALID_KEY 0xFFFFFFFFFFFFFFFFull

// XLA-matching sum of squares: rn(rn(rn(x^2)+rn(y^2))+rn(z^2)), NO fma fusion
__device__ __forceinline__ float sumsq_xla(float x, float y, float z) {
    return __fadd_rn(__fadd_rn(__fmul_rn(x, x), __fmul_rn(y, y)), __fmul_rn(z, z));
}

__global__ void radius_graph_kernel(const float* __restrict__ pos,
                                    const int* __restrict__ batch,
                                    float* __restrict__ out,
                                    int N) {
    int warp = (int)((blockIdx.x * blockDim.x + threadIdx.x) >> 5);
    int lane = threadIdx.x & 31;
    if (warp >= N) return;
    const int i = warp;
    const long long nk = (long long)N * KNB;

    const float xi = pos[3 * i + 0];
    const float yi = pos[3 * i + 1];
    const float zi = pos[3 * i + 2];
    const float sqi = sumsq_xla(xi, yi, zi);
    const int b = batch[i];

    // molecule range via binary search on sorted batch (uniform across warp)
    int lo, hi;
    {
        int l = 0, r = N;
        while (l < r) { int m = (l + r) >> 1; if (batch[m] < b) l = m + 1; else r = m; }
        lo = l;
    }
    {
        int l = lo, r = N;
        while (l < r) { int m = (l + r) >> 1; if (batch[m] <= b) l = m + 1; else r = m; }
        hi = l;
    }

    // per-lane candidate pool (registers, statically indexed)
    unsigned long long cand[MAXPL];
#pragma unroll
    for (int t = 0; t < MAXPL; t++) cand[t] = INVALID_KEY;

    const int nm = hi - lo;
    const int per = (nm + 31) >> 5;
    for (int t = 0; t < per; t++) {
        int j = lo + lane + (t << 5);
        if (j >= hi || j == i) continue;
        float xj = pos[3 * j + 0];
        float yj = pos[3 * j + 1];
        float zj = pos[3 * j + 2];
        // sq_j: XLA reduce style (mul + adds, no fma)
        float sqj = sumsq_xla(xj, yj, zj);
        // dot: cuBLAS SGEMM style sequential-K fma accumulation from 0
        // fma(x,x',0) == rn(x*x'), then fma(y..), fma(z..)
        float dot = __fmaf_rn(zi, zj, __fmaf_rn(yi, yj, __fmul_rn(xi, xj)));
        // combine UNcontracted: rn(rn(sqi+sqj) - rn(2*dot))
        float d2 = __fsub_rn(__fadd_rn(sqi, sqj), __fmul_rn(2.0f, dot));
        float dist = __fsqrt_rn(fmaxf(d2, 0.0f));
        if (dist <= CUTOFF) {
            unsigned long long key =
                (((unsigned long long)__float_as_uint(dist)) << 32) | (unsigned int)j;
            if (t < MAXPL) {
#pragma unroll
                for (int s = 0; s < MAXPL; s++) if (s == t) cand[s] = key;
            } else {
                // pathological huge molecule: evict lane-local max if new key smaller
                unsigned long long mx = cand[0]; int mxs = 0;
#pragma unroll
                for (int s = 1; s < MAXPL; s++) if (cand[s] > mx) { mx = cand[s]; mxs = s; }
                if (key < mx) {
#pragma unroll
                    for (int s = 0; s < MAXPL; s++) if (s == mxs) cand[s] = key;
                }
            }
        }
    }

    // K rounds of warp-wide argmin selection (exact top-K, ascending dist, lower j on ties)
    unsigned long long mykey = INVALID_KEY;
    for (int k = 0; k < KNB; k++) {
        unsigned long long v = cand[0];
#pragma unroll
        for (int s = 1; s < MAXPL; s++) { unsigned long long c = cand[s]; v = (c < v) ? c : v; }
#pragma unroll
        for (int off = 16; off > 0; off >>= 1) {
            unsigned long long o = __shfl_xor_sync(0xffffffffu, v, off);
            v = (o < v) ? o : v;
        }
        if (v == INVALID_KEY) break;   // uniform across warp
        if (lane == k) mykey = v;
#pragma unroll
        for (int s = 0; s < MAXPL; s++) if (cand[s] == v) cand[s] = INVALID_KEY;
    }

    // write edge slot e = i*K + lane
    const bool valid = (mykey != INVALID_KEY);
    const int j = valid ? (int)(unsigned int)(mykey & 0xFFFFFFFFull) : i;
    const long long e = (long long)i * KNB + lane;

    float vx = 0.0f, vy = 0.0f, vz = 0.0f;
    if (valid) {
        vx = __fsub_rn(pos[3 * j + 0], xi);
        vy = __fsub_rn(pos[3 * j + 1], yi);
        vz = __fsub_rn(pos[3 * j + 2], zi);
    }

    out[e]            = (float)i;          // src
    out[nk + e]       = (float)j;          // dst
    out[2 * nk + 3 * e + 0] = vx;          // edge_vec
    out[2 * nk + 3 * e + 1] = vy;
    out[2 * nk + 3 * e + 2] = vz;
    out[5 * nk + e]   = valid ? 1.0f : 0.0f;  // mask
}

extern "C" void kernel_launch(void* const* d_in, const int* in_sizes, int n_in,
                              void* d_out, int out_size) {
    const float* pos = (const float*)d_in[0];
    const int* batch = (const int*)d_in[1];
    float* out = (float*)d_out;
    int N = in_sizes[1];            // batch has one entry per atom
    (void)n_in; (void)out_size;

    const int warpsPerBlock = 8;    // 256 threads
    int blocks = (N + warpsPerBlock - 1) / warpsPerBlock;
    radius_graph_kernel<<<blocks, warpsPerBlock * 32>>>(pos, batch, out, N);
}

// round 4
// speedup vs baseline: 2.0319x; 2.0319x over previous
#include <cuda_runtime.h>
#include <cuda_bf16.h>

#define KNB 32
#define CUTOFF 5.0f
#define INVALID_KEY 0xFFFFFFFFFFFFFFFFull
#define FULLMASK 0xFFFFFFFFu

// XLA-matching sum of squares: rn(rn(rn(x^2)+rn(y^2))+rn(z^2)), NO fma fusion
__device__ __forceinline__ float sumsq_xla(float x, float y, float z) {
    return __fadd_rn(__fadd_rn(__fmul_rn(x, x), __fmul_rn(y, y)), __fmul_rn(z, z));
}

__device__ __forceinline__ unsigned long long shfl_xor64(unsigned long long v, int m) {
    return __shfl_xor_sync(FULLMASK, v, m);
}

// full bitonic sort of 32 keys (one per lane), ascending by lane
__device__ __forceinline__ void bitonic_sort32(unsigned long long& v, int lane) {
#pragma unroll
    for (int k = 2; k <= 32; k <<= 1) {
#pragma unroll
        for (int j = k >> 1; j > 0; j >>= 1) {
            unsigned long long o = shfl_xor64(v, j);
            bool up = ((lane & k) == 0);
            bool takeMin = (((lane & j) == 0) == up);
            unsigned long long mn = (v < o) ? v : o;
            unsigned long long mx = (v < o) ? o : v;
            v = takeMin ? mn : mx;
        }
    }
}

// bitonic merge (input bitonic), sorts ascending by lane
__device__ __forceinline__ void bitonic_merge32(unsigned long long& v, int lane) {
#pragma unroll
    for (int j = 16; j > 0; j >>= 1) {
        unsigned long long o = shfl_xor64(v, j);
        bool takeMin = ((lane & j) == 0);
        unsigned long long mn = (v < o) ? v : o;
        unsigned long long mx = (v < o) ? o : v;
        v = takeMin ? mn : mx;
    }
}

__global__ void radius_graph_kernel(const float* __restrict__ pos,
                                    const int* __restrict__ batch,
                                    float* __restrict__ out,
                                    int N) {
    int warp = (int)((blockIdx.x * blockDim.x + threadIdx.x) >> 5);
    int lane = threadIdx.x & 31;
    if (warp >= N) return;
    const int i = warp;
    const int nk = N * KNB;   // 262144 for N=8192: fits int32

    const float xi = pos[3 * i + 0];
    const float yi = pos[3 * i + 1];
    const float zi = pos[3 * i + 2];
    const float sqi = sumsq_xla(xi, yi, zi);
    const int b = batch[i];

    // molecule range via binary search on sorted batch (uniform across warp)
    int lo, hi;
    {
        int l = 0, r = N;
        while (l < r) { int m = (l + r) >> 1; if (batch[m] < b) l = m + 1; else r = m; }
        lo = l;
    }
    {
        int l = lo, r = N;
        while (l < r) { int m = (l + r) >> 1; if (batch[m] <= b) l = m + 1; else r = m; }
        hi = l;
    }

    // running sorted top-32 (lane k holds k-th smallest key), init invalid
    unsigned long long L = INVALID_KEY;

    const int nm = hi - lo;
    const int per = (nm + 31) >> 5;
    for (int t = 0; t < per; t++) {
        int j = lo + lane + (t << 5);
        unsigned long long key = INVALID_KEY;
        if (j < hi && j != i) {
            float xj = pos[3 * j + 0];
            float yj = pos[3 * j + 1];
            float zj = pos[3 * j + 2];
            // sq_j: XLA reduce style (mul + adds, no fma)
            float sqj = sumsq_xla(xj, yj, zj);
            // dot: cuBLAS SGEMM style sequential-K fma accumulation
            float dot = __fmaf_rn(zi, zj, __fmaf_rn(yi, yj, __fmul_rn(xi, xj)));
            // combine UNcontracted: rn(rn(sqi+sqj) - rn(2*dot))
            float d2 = __fsub_rn(__fadd_rn(sqi, sqj), __fmul_rn(2.0f, dot));
            float dist = __fsqrt_rn(fmaxf(d2, 0.0f));
            if (dist <= CUTOFF) {
                key = (((unsigned long long)__float_as_uint(dist)) << 32) | (unsigned int)j;
            }
        }
        // skip fully-empty batches cheaply
        if (__ballot_sync(FULLMASK, key != INVALID_KEY) == 0u) continue;

        bitonic_sort32(key, lane);          // batch sorted ascending
        if (t == 0) {
            L = key;
        } else {
            // keep lowest 32 of (L ∪ batch): reverse batch, elementwise min, re-merge
            unsigned long long brev = shfl_xor64(key, 31);
            L = (L < brev) ? L : brev;      // bitonic sequence
            bitonic_merge32(L, lane);       // sorted ascending again
        }
    }

    // lane k owns output slot k: k-th nearest neighbor (exact top_k order)
    const unsigned long long mykey = L;
    const bool valid = (mykey != INVALID_KEY);
    const int j = valid ? (int)(unsigned int)(mykey & 0xFFFFFFFFull) : i;
    const int e = i * KNB + lane;

    float vx = 0.0f, vy = 0.0f, vz = 0.0f;
    if (valid) {
        vx = __fsub_rn(pos[3 * j + 0], xi);
        vy = __fsub_rn(pos[3 * j + 1], yi);
        vz = __fsub_rn(pos[3 * j + 2], zi);
    }

    out[e]                  = (float)i;            // src
    out[nk + e]             = (float)j;            // dst
    out[2 * nk + 3 * e + 0] = vx;                  // edge_vec
    out[2 * nk + 3 * e + 1] = vy;
    out[2 * nk + 3 * e + 2] = vz;
    out[5 * nk + e]         = valid ? 1.0f : 0.0f; // mask
}

extern "C" void kernel_launch(void* const* d_in, const int* in_sizes, int n_in,
                              void* d_out, int out_size) {
    const float* pos = (const float*)d_in[0];
    const int* batch = (const int*)d_in[1];
    float* out = (float*)d_out;
    int N = in_sizes[1];            // batch has one entry per atom
    (void)n_in; (void)out_size;

    const int warpsPerBlock = 8;    // 256 threads
    int blocks = (N + warpsPerBlock - 1) / warpsPerBlock;
    radius_graph_kernel<<<blocks, warpsPerBlock * 32>>>(pos, batch, out, N);
}

// round 5
// speedup vs baseline: 2.3961x; 1.1792x over previous
#include <cuda_runtime.h>
#include <cuda_bf16.h>

#define KNB 32
#define CUTOFF 5.0f
#define INVALID_KEY 0xFFFFFFFFFFFFFFFFull
#define FULLMASK 0xFFFFFFFFu

// XLA-matching sum of squares: rn(rn(rn(x^2)+rn(y^2))+rn(z^2)), NO fma fusion
__device__ __forceinline__ float sumsq_xla(float x, float y, float z) {
    return __fadd_rn(__fadd_rn(__fmul_rn(x, x), __fmul_rn(y, y)), __fmul_rn(z, z));
}

__device__ __forceinline__ unsigned long long shfl_xor64(unsigned long long v, int m) {
    return __shfl_xor_sync(FULLMASK, v, m);
}
__device__ __forceinline__ unsigned long long shfl_idx64(unsigned long long v, int s) {
    return __shfl_sync(FULLMASK, v, s);
}

// full bitonic sort of 32 keys (one per lane), ascending by lane
__device__ __forceinline__ void bitonic_sort32(unsigned long long& v, int lane) {
#pragma unroll
    for (int k = 2; k <= 32; k <<= 1) {
#pragma unroll
        for (int j = k >> 1; j > 0; j >>= 1) {
            unsigned long long o = shfl_xor64(v, j);
            bool up = ((lane & k) == 0);
            bool takeMin = (((lane & j) == 0) == up);
            if ((o < v) == takeMin) v = o;
        }
    }
}

// bitonic merge (input bitonic), sorts ascending by lane
__device__ __forceinline__ void bitonic_merge32(unsigned long long& v, int lane) {
#pragma unroll
    for (int j = 16; j > 0; j >>= 1) {
        unsigned long long o = shfl_xor64(v, j);
        bool takeMin = ((lane & j) == 0);
        if ((o < v) == takeMin) v = o;
    }
}

// flush buffer P into sorted top-32 list L (keeps lowest 32 of union)
__device__ __forceinline__ void flush_merge(unsigned long long& L,
                                            unsigned long long& P, int lane) {
    bitonic_sort32(P, lane);
    unsigned long long brev = shfl_xor64(P, 31);   // reverse -> descending
    L = (L < brev) ? L : brev;                     // elementwise min: bitonic
    bitonic_merge32(L, lane);                      // sorted ascending
}

__global__ void __launch_bounds__(128)
radius_graph_kernel(const float* __restrict__ pos,
                    const int* __restrict__ batch,
                    float* __restrict__ out,
                    int N) {
    int warp = (int)((blockIdx.x * blockDim.x + threadIdx.x) >> 5);
    int lane = threadIdx.x & 31;
    if (warp >= N) return;
    const int i = warp;
    const int nk = N * KNB;

    const float xi = pos[3 * i + 0];
    const float yi = pos[3 * i + 1];
    const float zi = pos[3 * i + 2];
    const float sqi = sumsq_xla(xi, yi, zi);
    const int b = batch[i];

    // molecule range via binary search on sorted batch (uniform across warp)
    int lo, hi;
    {
        int l = 0, r = N;
        while (l < r) { int m = (l + r) >> 1; if (batch[m] < b) l = m + 1; else r = m; }
        lo = l;
    }
    {
        int l = lo, r = N;
        while (l < r) { int m = (l + r) >> 1; if (batch[m] <= b) l = m + 1; else r = m; }
        hi = l;
    }

    unsigned long long L = INVALID_KEY;        // sorted top-32 (ascending by lane)
    unsigned long long thresh = INVALID_KEY;   // current 32nd-smallest (L[31])
    unsigned long long P = INVALID_KEY;        // compaction buffer
    int cnt = 0;                               // warp-uniform fill count of P

    const int nm = hi - lo;
    const int per = (nm + 31) >> 5;
    for (int t = 0; t < per; t++) {
        int j = lo + lane + (t << 5);
        unsigned long long key = INVALID_KEY;
        if (j < hi && j != i) {
            float xj = pos[3 * j + 0];
            float yj = pos[3 * j + 1];
            float zj = pos[3 * j + 2];
            float sqj = sumsq_xla(xj, yj, zj);
            float dot = __fmaf_rn(zi, zj, __fmaf_rn(yi, yj, __fmul_rn(xi, xj)));
            float d2 = __fsub_rn(__fadd_rn(sqi, sqj), __fmul_rn(2.0f, dot));
            float dist = __fsqrt_rn(fmaxf(d2, 0.0f));
            if (dist <= CUTOFF) {
                unsigned long long k64 =
                    (((unsigned long long)__float_as_uint(dist)) << 32) | (unsigned int)j;
                if (k64 < thresh) key = k64;   // prune vs current 32nd smallest
            }
        }
        unsigned bal = __ballot_sync(FULLMASK, key != INVALID_KEY);
        if (!bal) continue;
        int nv = __popc(bal);
        int space = 32 - cnt;   // >= 1 always (flush keeps cnt < 32)

        // route valid candidates into buffer slots cnt..cnt+nv-1
        int r = lane - cnt;
        unsigned src = __fns(bal, 0, r + 1);
        unsigned long long moved = shfl_idx64(key, (int)(src & 31u));
        if (r >= 0 && r < nv && r < space) P = moved;

        if (nv >= space) {
            // buffer full: flush into L, update threshold
            flush_merge(L, P, lane);
            thresh = shfl_idx64(L, 31);
            // leftover candidates (ranks space..nv-1) restart the buffer
            int nv2 = nv - space;
            unsigned src2 = __fns(bal, 0, lane + space + 1);
            unsigned long long moved2 = shfl_idx64(key, (int)(src2 & 31u));
            P = (lane < nv2) ? moved2 : INVALID_KEY;
            cnt = nv2;
        } else {
            cnt += nv;
        }
    }
    if (cnt > 0) flush_merge(L, P, lane);

    // lane k owns output slot k: k-th nearest neighbor (exact top_k order)
    const unsigned long long mykey = L;
    const bool valid = (mykey != INVALID_KEY);
    const int j = valid ? (int)(unsigned int)(mykey & 0xFFFFFFFFull) : i;
    const int e = i * KNB + lane;

    float vx = 0.0f, vy = 0.0f, vz = 0.0f;
    if (valid) {
        vx = __fsub_rn(pos[3 * j + 0], xi);
        vy = __fsub_rn(pos[3 * j + 1], yi);
        vz = __fsub_rn(pos[3 * j + 2], zi);
    }

    out[e]                  = (float)i;            // src
    out[nk + e]             = (float)j;            // dst
    out[2 * nk + 3 * e + 0] = vx;                  // edge_vec
    out[2 * nk + 3 * e + 1] = vy;
    out[2 * nk + 3 * e + 2] = vz;
    out[5 * nk + e]         = valid ? 1.0f : 0.0f; // mask
}

extern "C" void kernel_launch(void* const* d_in, const int* in_sizes, int n_in,
                              void* d_out, int out_size) {
    const float* pos = (const float*)d_in[0];
    const int* batch = (const int*)d_in[1];
    float* out = (float*)d_out;
    int N = in_sizes[1];            // batch has one entry per atom
    (void)n_in; (void)out_size;

    const int warpsPerBlock = 4;    // 128 threads: finer scheduling, smaller tail
    int blocks = (N + warpsPerBlock - 1) / warpsPerBlock;
    radius_graph_kernel<<<blocks, warpsPerBlock * 32>>>(pos, batch, out, N);
}

// round 6
// speedup vs baseline: 2.6875x; 1.1216x over previous
#include <cuda_runtime.h>
#include <cuda_bf16.h>

#define KNB 32
#define CUTOFF 5.0f
#define INVALID_KEY 0xFFFFFFFFFFFFFFFFull
#define FULLMASK 0xFFFFFFFFu

// XLA-matching sum of squares: rn(rn(rn(x^2)+rn(y^2))+rn(z^2)), NO fma fusion
__device__ __forceinline__ float sumsq_xla(float x, float y, float z) {
    return __fadd_rn(__fadd_rn(__fmul_rn(x, x), __fmul_rn(y, y)), __fmul_rn(z, z));
}

__device__ __forceinline__ unsigned long long shfl_xor64(unsigned long long v, int m) {
    return __shfl_xor_sync(FULLMASK, v, m);
}
__device__ __forceinline__ unsigned long long shfl_idx64(unsigned long long v, int s) {
    return __shfl_sync(FULLMASK, v, s);
}

// full bitonic sort of 32 keys (one per lane), ascending by lane
__device__ __forceinline__ void bitonic_sort32(unsigned long long& v, int lane) {
#pragma unroll
    for (int k = 2; k <= 32; k <<= 1) {
#pragma unroll
        for (int j = k >> 1; j > 0; j >>= 1) {
            unsigned long long o = shfl_xor64(v, j);
            bool up = ((lane & k) == 0);
            bool takeMin = (((lane & j) == 0) == up);
            if ((o < v) == takeMin) v = o;
        }
    }
}

// bitonic merge (input bitonic), sorts ascending by lane
__device__ __forceinline__ void bitonic_merge32(unsigned long long& v, int lane) {
#pragma unroll
    for (int j = 16; j > 0; j >>= 1) {
        unsigned long long o = shfl_xor64(v, j);
        bool takeMin = ((lane & j) == 0);
        if ((o < v) == takeMin) v = o;
    }
}

// accumulate this iteration's ballot'd candidates into P; flush into L when full
__device__ __forceinline__ void accum(unsigned long long& L, unsigned long long& P,
                                      int& cnt, unsigned long long& thresh, bool& first,
                                      unsigned long long key, unsigned bal, int lane) {
    int nv = __popc(bal);
    int space = 32 - cnt;                 // >= 1 (flush keeps cnt < 32)
    int r = lane - cnt;
    unsigned src = __fns(bal, 0, r + 1);
    unsigned long long moved = shfl_idx64(key, (int)(src & 31u));
    if (r >= 0 && r < nv && r < space) P = moved;

    if (nv >= space) {
        bitonic_sort32(P, lane);
        if (first) {
            L = P;                         // fast path: merge with empty L is identity
            first = false;
        } else {
            unsigned long long brev = shfl_xor64(P, 31);
            L = (L < brev) ? L : brev;     // bitonic
            bitonic_merge32(L, lane);
        }
        thresh = shfl_idx64(L, 31);
        int nv2 = nv - space;
        unsigned src2 = __fns(bal, 0, lane + space + 1);
        unsigned long long moved2 = shfl_idx64(key, (int)(src2 & 31u));
        P = (lane < nv2) ? moved2 : INVALID_KEY;
        cnt = nv2;
    } else {
        cnt += nv;
    }
}

__device__ __forceinline__ void final_flush(unsigned long long& L, unsigned long long& P,
                                            int cnt, bool first, int lane) {
    if (cnt > 0) {
        bitonic_sort32(P, lane);
        if (first) {
            L = P;
        } else {
            unsigned long long brev = shfl_xor64(P, 31);
            L = (L < brev) ? L : brev;
            bitonic_merge32(L, lane);
        }
    }
}

__global__ void __launch_bounds__(128)
radius_graph_kernel(const float* __restrict__ pos,
                    const int* __restrict__ batch,
                    float* __restrict__ out,
                    int N) {
    int w = (int)((blockIdx.x * blockDim.x + threadIdx.x) >> 5);
    int lane = threadIdx.x & 31;
    const int i0 = 2 * w;
    if (i0 >= N) return;
    const int i1 = i0 + 1;
    const bool has1 = (i1 < N);
    const int nk = N * KNB;

    const float x0 = pos[3 * i0 + 0], y0 = pos[3 * i0 + 1], z0 = pos[3 * i0 + 2];
    const float sq0 = sumsq_xla(x0, y0, z0);
    const int b0 = batch[i0];

    float x1 = x0, y1 = y0, z1 = z0, sq1 = sq0;
    int b1 = b0;
    if (has1) {
        x1 = pos[3 * i1 + 0]; y1 = pos[3 * i1 + 1]; z1 = pos[3 * i1 + 2];
        sq1 = sumsq_xla(x1, y1, z1);
        b1 = batch[i1];
    }

    // LO = first index of molecule b0; HI = one past last index of molecule b1
    int LO, HI;
    {
        int l = 0, r = N;
        while (l < r) { int m = (l + r) >> 1; if (batch[m] < b0) l = m + 1; else r = m; }
        LO = l;
    }
    {
        int l = LO, r = N;
        while (l < r) { int m = (l + r) >> 1; if (batch[m] <= b1) l = m + 1; else r = m; }
        HI = l;
    }
    // per-atom ranges: if molecules differ, the split is exactly at i1 (batch sorted)
    int hi0 = (b0 == b1) ? HI : i1;
    int lo1 = (b0 == b1) ? LO : i1;

    unsigned long long L0 = INVALID_KEY, L1 = INVALID_KEY;
    unsigned long long P0 = INVALID_KEY, P1 = INVALID_KEY;
    unsigned long long th0 = INVALID_KEY, th1 = INVALID_KEY;
    int cnt0 = 0, cnt1 = 0;
    bool first0 = true, first1 = true;

    const int per = (HI - LO + 31) >> 5;
    for (int t = 0; t < per; t++) {
        int j = LO + lane + (t << 5);
        unsigned long long key0 = INVALID_KEY, key1 = INVALID_KEY;
        if (j < HI) {
            float xj = pos[3 * j + 0];
            float yj = pos[3 * j + 1];
            float zj = pos[3 * j + 2];
            float sqj = sumsq_xla(xj, yj, zj);
            if (j < hi0 && j != i0) {
                float dot = __fmaf_rn(z0, zj, __fmaf_rn(y0, yj, __fmul_rn(x0, xj)));
                float d2 = __fsub_rn(__fadd_rn(sq0, sqj), __fmul_rn(2.0f, dot));
                float dist = __fsqrt_rn(fmaxf(d2, 0.0f));
                if (dist <= CUTOFF) {
                    unsigned long long k64 =
                        (((unsigned long long)__float_as_uint(dist)) << 32) | (unsigned int)j;
                    if (k64 < th0) key0 = k64;
                }
            }
            if (has1 && j >= lo1 && j != i1) {
                float dot = __fmaf_rn(z1, zj, __fmaf_rn(y1, yj, __fmul_rn(x1, xj)));
                float d2 = __fsub_rn(__fadd_rn(sq1, sqj), __fmul_rn(2.0f, dot));
                float dist = __fsqrt_rn(fmaxf(d2, 0.0f));
                if (dist <= CUTOFF) {
                    unsigned long long k64 =
                        (((unsigned long long)__float_as_uint(dist)) << 32) | (unsigned int)j;
                    if (k64 < th1) key1 = k64;
                }
            }
        }
        unsigned bal0 = __ballot_sync(FULLMASK, key0 != INVALID_KEY);
        unsigned bal1 = __ballot_sync(FULLMASK, key1 != INVALID_KEY);
        if (bal0) accum(L0, P0, cnt0, th0, first0, key0, bal0, lane);
        if (bal1) accum(L1, P1, cnt1, th1, first1, key1, bal1, lane);
    }
    final_flush(L0, P0, cnt0, first0, lane);
    final_flush(L1, P1, cnt1, first1, lane);

    // lane k owns output slot k: k-th nearest neighbor (exact top_k order)
    {
        const bool valid = (L0 != INVALID_KEY);
        const int j = valid ? (int)(unsigned int)(L0 & 0xFFFFFFFFull) : i0;
        const int e = i0 * KNB + lane;
        float vx = 0.0f, vy = 0.0f, vz = 0.0f;
        if (valid) {
            vx = __fsub_rn(pos[3 * j + 0], x0);
            vy = __fsub_rn(pos[3 * j + 1], y0);
            vz = __fsub_rn(pos[3 * j + 2], z0);
        }
        out[e]                  = (float)i0;
        out[nk + e]             = (float)j;
        out[2 * nk + 3 * e + 0] = vx;
        out[2 * nk + 3 * e + 1] = vy;
        out[2 * nk + 3 * e + 2] = vz;
        out[5 * nk + e]         = valid ? 1.0f : 0.0f;
    }
    if (has1) {
        const bool valid = (L1 != INVALID_KEY);
        const int j = valid ? (int)(unsigned int)(L1 & 0xFFFFFFFFull) : i1;
        const int e = i1 * KNB + lane;
        float vx = 0.0f, vy = 0.0f, vz = 0.0f;
        if (valid) {
            vx = __fsub_rn(pos[3 * j + 0], x1);
            vy = __fsub_rn(pos[3 * j + 1], y1);
            vz = __fsub_rn(pos[3 * j + 2], z1);
        }
        out[e]                  = (float)i1;
        out[nk + e]             = (float)j;
        out[2 * nk + 3 * e + 0] = vx;
        out[2 * nk + 3 * e + 1] = vy;
        out[2 * nk + 3 * e + 2] = vz;
        out[5 * nk + e]         = valid ? 1.0f : 0.0f;
    }
}

extern "C" void kernel_launch(void* const* d_in, const int* in_sizes, int n_in,
                              void* d_out, int out_size) {
    const float* pos = (const float*)d_in[0];
    const int* batch = (const int*)d_in[1];
    float* out = (float*)d_out;
    int N = in_sizes[1];            // batch has one entry per atom
    (void)n_in; (void)out_size;

    int nwarps = (N + 1) / 2;       // two atoms per warp
    const int warpsPerBlock = 4;    // 128 threads
    int blocks = (nwarps + warpsPerBlock - 1) / warpsPerBlock;
    radius_graph_kernel<<<blocks, warpsPerBlock * 32>>>(pos, batch, out, N);
}